// round 5
// baseline (speedup 1.0000x reference)
#include <cuda_runtime.h>
#include <cuda_bf16.h>
#include <math.h>

// Problem constants
#define BB   32
#define TT   4096
#define DZC  128
#define NDC  32
#define DHC  128
#define GG   384            // 3*DZ
#define IND  192            // 2*ND + DH

// ---------------- scratch (no cudaMalloc allowed) ----------------
// +2*GG pad: scan prefetches 2 steps ahead
__device__ float g_gi[(size_t)BB * TT * GG + 2 * GG];

// ---------------- packed fp32x2 helpers (sm_100+) ----------------
__device__ __forceinline__ void fma2(unsigned long long& d,
                                     unsigned long long a,
                                     unsigned long long b) {
    asm("fma.rn.f32x2 %0, %1, %2, %0;" : "+l"(d) : "l"(a), "l"(b));
}
__device__ __forceinline__ void add2(unsigned long long& d, unsigned long long a) {
    asm("add.rn.f32x2 %0, %0, %1;" : "+l"(d) : "l"(a));
}
__device__ __forceinline__ unsigned long long dup2(float a) {
    unsigned long long r;
    asm("mov.b64 %0, {%1, %1};" : "=l"(r) : "f"(a));
    return r;
}
__device__ __forceinline__ void unpk(unsigned long long v, float& x, float& y) {
    asm("mov.b64 {%0, %1}, %2;" : "=f"(x), "=f"(y) : "l"(v));
}
__device__ __forceinline__ float ex2f_(float x) {
    float y; asm("ex2.approx.f32 %0, %1;" : "=f"(y) : "f"(x)); return y;
}
__device__ __forceinline__ float rcpf_(float x) {
    float y; asm("rcp.approx.f32 %0, %1;" : "=f"(y) : "f"(x)); return y;
}
__device__ __forceinline__ float sigmoidf_(float x) {
    float e = ex2f_(-1.4426950408889634f * x);
    return rcpf_(1.0f + e);
}
__device__ __forceinline__ float tanhf_(float x) {
    float xc = fminf(fmaxf(x, -20.0f), 20.0f);
    float e = ex2f_(-2.8853900817779268f * xc);   // exp(-2x)
    return (1.0f - e) * rcpf_(1.0f + e);
}

// =====================================================================
// Kernel 1: gi_all[bt][g] = sum_k x[bt][k] * W_ih[g][k] + b_ih[g]
// (unchanged — scan change isolated)
// =====================================================================
#define Bb 128
#define BN 128
#define BK 16

__global__ __launch_bounds__(256) void gi_gemm_kernel(
    const float* __restrict__ Y, const float* __restrict__ M,
    const float* __restrict__ H, const float* __restrict__ W,
    const float* __restrict__ bias, float* __restrict__ gi)
{
    __shared__ __align__(16) float As[2][BK][Bb];
    __shared__ __align__(16) float Bs[2][BK][BN];

    const int tid = threadIdx.x;
    const int bt0 = blockIdx.x * Bb;
    const int g0  = blockIdx.y * BN;
    const int tx = tid & 15;      // n-dim
    const int ty = tid >> 4;      // m-dim

    unsigned long long acc[8][4];
    #pragma unroll
    for (int i = 0; i < 8; i++)
        #pragma unroll
        for (int j = 0; j < 4; j++) acc[i][j] = 0ull;

    auto loadA = [&](int stage, int kc) {
        #pragma unroll
        for (int i = 0; i < 2; i++) {
            int e  = tid + 256 * i;
            int m  = e & 127;
            int k4 = e >> 7;
            int kk = kc * BK + k4 * 4;
            int bt = bt0 + m;
            float4 v;
            if (kk < 32)       v = *(const float4*)(Y + (size_t)bt * NDC + kk);
            else if (kk < 64)  v = *(const float4*)(M + (size_t)bt * NDC + (kk - 32));
            else               v = *(const float4*)(H + (size_t)bt * DHC + (kk - 64));
            As[stage][k4 * 4 + 0][m] = v.x;
            As[stage][k4 * 4 + 1][m] = v.y;
            As[stage][k4 * 4 + 2][m] = v.z;
            As[stage][k4 * 4 + 3][m] = v.w;
        }
    };
    auto loadB = [&](int stage, int kc) {
        #pragma unroll
        for (int i = 0; i < 2; i++) {
            int e  = tid + 256 * i;
            int g  = e & 127;
            int k4 = e >> 7;
            int kk = kc * BK + k4 * 4;
            float4 v = *(const float4*)(W + (size_t)(g0 + g) * IND + kk);
            Bs[stage][k4 * 4 + 0][g] = v.x;
            Bs[stage][k4 * 4 + 1][g] = v.y;
            Bs[stage][k4 * 4 + 2][g] = v.z;
            Bs[stage][k4 * 4 + 3][g] = v.w;
        }
    };

    loadA(0, 0); loadB(0, 0);
    __syncthreads();

    const int NKC = IND / BK;   // 12
    for (int kc = 0; kc < NKC; kc++) {
        int cur = kc & 1, nxt = cur ^ 1;
        if (kc + 1 < NKC) { loadA(nxt, kc + 1); loadB(nxt, kc + 1); }
        #pragma unroll
        for (int k = 0; k < BK; k++) {
            float a[8];
            *(float4*)&a[0] = *(const float4*)&As[cur][k][ty * 8];
            *(float4*)&a[4] = *(const float4*)&As[cur][k][ty * 8 + 4];
            unsigned long long b[4];
            {
                ulonglong2 b0 = *(const ulonglong2*)&Bs[cur][k][tx * 8];
                ulonglong2 b1 = *(const ulonglong2*)&Bs[cur][k][tx * 8 + 4];
                b[0] = b0.x; b[1] = b0.y; b[2] = b1.x; b[3] = b1.y;
            }
            #pragma unroll
            for (int i = 0; i < 8; i++) {
                unsigned long long ad = dup2(a[i]);
                fma2(acc[i][0], ad, b[0]);
                fma2(acc[i][1], ad, b[1]);
                fma2(acc[i][2], ad, b[2]);
                fma2(acc[i][3], ad, b[3]);
            }
        }
        __syncthreads();
    }

    float bia[8];
    *(float4*)&bia[0] = *(const float4*)(bias + g0 + tx * 8);
    *(float4*)&bia[4] = *(const float4*)(bias + g0 + tx * 8 + 4);

    #pragma unroll
    for (int i = 0; i < 8; i++) {
        float c[8];
        unpk(acc[i][0], c[0], c[1]);
        unpk(acc[i][1], c[2], c[3]);
        unpk(acc[i][2], c[4], c[5]);
        unpk(acc[i][3], c[6], c[7]);
        #pragma unroll
        for (int j = 0; j < 8; j++) c[j] += bia[j];
        int bt = bt0 + ty * 8 + i;
        float* out = gi + (size_t)bt * GG + g0 + tx * 8;
        *(float4*)(out)     = *(float4*)&c[0];
        *(float4*)(out + 4) = *(float4*)&c[4];
    }
}

// =====================================================================
// Kernel 2: GRU scan. 512 threads, ONE barrier per step, DOUBLE-BUFFERED
// z_d exchange (race-free: write(end t) -> bar(t+1) -> read(t+1)).
// tid -> (j = tid>>2, q = tid&3). Thread (j,q) holds K-quarter
// [32q,32q+32) of W_hh rows {j, 128+j, 256+j} in regs (48 u64).
// Partials reduced across the 4 q-lanes with 2x shfl.xor.
// zbuf q-swizzled: value k at float index 4*(k>>5) + 16*((k>>2)&7) + (k&3)
// so the 4 q-lane LDS.128 reads per chunk are conflict-free.
// =====================================================================
__global__ __launch_bounds__(512, 1) void gru_scan_kernel(
    const float* __restrict__ z0, const float* __restrict__ t_dyn,
    const int* __restrict__ dyn_lens,
    const float* __restrict__ W_hh, const float* __restrict__ b_hh,
    const float* __restrict__ log_gamma,
    float* __restrict__ z_final, float* __restrict__ Z_traj)
{
    __shared__ __align__(16) float dtbuf[TT + 4];   // dt per step (+pad)
    __shared__ __align__(16) float zbA[DZC];        // z_d double buffer
    __shared__ __align__(16) float zbB[DZC];

    const int b   = blockIdx.x;
    const int tid = threadIdx.x;
    const int j   = tid >> 2;     // state dim 0..127
    const int q   = tid & 3;      // K-quarter 0..3

    // ---- dtbuf: dt[t] = max(ts[t]-ts[t-1],0), dt[0]=0, dt[TT]=0 ----
    {
        const float* tp = t_dyn + (size_t)b * TT;
        for (int i = tid; i < TT; i += 512) {
            float cur = __ldg(tp + i);
            float prv = (i > 0) ? __ldg(tp + i - 1) : cur;
            dtbuf[i] = fmaxf(cur - prv, 0.0f);
        }
        if (tid == 0) dtbuf[TT] = 0.0f;
    }

    // ---- weights: rows {j, 128+j, 256+j}, K slice [32q, 32q+32) ----
    unsigned long long Wr[16], Wu[16], Wn[16];
    {
        const ulonglong2* wr = (const ulonglong2*)(W_hh + (size_t)j * DZC + 32 * q);
        const ulonglong2* wu = (const ulonglong2*)(W_hh + (size_t)(128 + j) * DZC + 32 * q);
        const ulonglong2* wn = (const ulonglong2*)(W_hh + (size_t)(256 + j) * DZC + 32 * q);
        #pragma unroll
        for (int i = 0; i < 8; i++) {
            ulonglong2 a = wr[i]; Wr[2*i] = a.x; Wr[2*i+1] = a.y;
            ulonglong2 c = wu[i]; Wu[2*i] = c.x; Wu[2*i+1] = c.y;
            ulonglong2 d = wn[i]; Wn[2*i] = d.x; Wn[2*i+1] = d.y;
        }
    }
    // bias inject (once per gate, pre-reduce): q0->bh_r, q1->bh_u, q2->bh_n
    const float bhq = (q < 3) ? b_hh[q * DZC + j] : 0.0f;
    const int   len = dyn_lens[b];

    float lg  = log_gamma[j];
    float sp  = (lg > 20.0f) ? lg : log1pf(expf(lg));   // softplus
    const float gje = -1.4426950408889634f * sp;        // pre-scaled for ex2

    // gi stream: q0->r row, q1->u row, q2&q3->n row (q3 duplicates q2)
    const int grow = (q < 3) ? q : 2;
    const float* p_gi = g_gi + (size_t)b * TT * GG + grow * DZC + j;
    float gi_c = __ldg(p_gi);
    float gi_1 = __ldg(p_gi + GG);
    p_gi += 2 * GG;

    // q-swizzled zbuf indices (see header comment)
    const int zwr_idx = (((j >> 5) + 4 * ((j >> 2) & 7)) << 2) + (j & 3);
    const int zrd_off = q;   // ull2 base offset; chunk c at [zrd_off + 4c]

    float* zp = Z_traj + (size_t)b * TT * DZC + j;   // q3 stores
    const unsigned src_n = (tid & ~3u) | 2u;          // lane holding gi_n

    // init: z_d(0) = z0 (dt[0]=0)
    float zdj = z0[(size_t)b * DZC + j];
    if (q == 0) zbA[zwr_idx] = zdj;

    auto step = [&](int t, const float* __restrict__ zr, float* __restrict__ zw) {
        __syncthreads();   // zr(t) visible; zw safe to overwrite

        // off-critical-path: decay for t+1, gi prefetch t+2
        float edn  = ex2f_(gje * dtbuf[t + 1]);
        float gi_2 = __ldg(p_gi);
        p_gi += GG;

        // dot over K-quarter: 8 LDS.128 shared across 3 rows, 48 fma2
        unsigned long long ar0 = 0, ar1 = 0, au0 = 0, au1 = 0, an0 = 0, an1 = 0;
        const ulonglong2* zc = (const ulonglong2*)zr + zrd_off;
        #pragma unroll
        for (int i = 0; i < 8; i += 2) {
            ulonglong2 v0 = zc[i * 4];
            ulonglong2 v1 = zc[(i + 1) * 4];
            fma2(ar0, Wr[2*i],   v0.x); fma2(ar0, Wr[2*i+1], v0.y);
            fma2(au0, Wu[2*i],   v0.x); fma2(au0, Wu[2*i+1], v0.y);
            fma2(an0, Wn[2*i],   v0.x); fma2(an0, Wn[2*i+1], v0.y);
            fma2(ar1, Wr[2*i+2], v1.x); fma2(ar1, Wr[2*i+3], v1.y);
            fma2(au1, Wu[2*i+2], v1.x); fma2(au1, Wu[2*i+3], v1.y);
            fma2(an1, Wn[2*i+2], v1.x); fma2(an1, Wn[2*i+3], v1.y);
        }
        add2(ar0, ar1); add2(au0, au1); add2(an0, an1);
        float r0, r1, u0, u1, n0, n1;
        unpk(ar0, r0, r1); unpk(au0, u0, u1); unpk(an0, n0, n1);
        float Sr = r0 + r1, Su = u0 + u1, Sn = n0 + n1;

        // inject gi+bias once per gate (gi_n kept separate for tanh)
        if (q == 0)      Sr += gi_c + bhq;
        else if (q == 1) Su += gi_c + bhq;
        else if (q == 2) Sn += bhq;

        float gin = __shfl_sync(0xffffffffu, gi_c, src_n);

        // reduce across the 4 q-lanes
        Sr += __shfl_xor_sync(0xffffffffu, Sr, 1);
        Su += __shfl_xor_sync(0xffffffffu, Su, 1);
        Sn += __shfl_xor_sync(0xffffffffu, Sn, 1);
        Sr += __shfl_xor_sync(0xffffffffu, Sr, 2);
        Su += __shfl_xor_sync(0xffffffffu, Su, 2);
        Sn += __shfl_xor_sync(0xffffffffu, Sn, 2);

        // gates + epilogue (all lanes, identical)
        float rr = sigmoidf_(Sr);
        float uu = sigmoidf_(Su);
        float nn = tanhf_(gin + rr * Sn);
        float znew = nn + uu * (zdj - nn);
        float zj   = (t < len) ? znew : zdj;
        if (q == 3) *zp = zj;
        zp += DZC;

        zdj = zj * edn;                  // z_d for t+1 (dt[TT]=0 -> edn=1)
        if (q == 0) zw[zwr_idx] = zdj;

        gi_c = gi_1; gi_1 = gi_2;
    };

    for (int t = 0; t < TT; t += 2) {
        step(t,     zbA, zbB);
        step(t + 1, zbB, zbA);
    }

    // dt[TT]=0 -> zdj == last zj
    if (q == 3) z_final[(size_t)b * DZC + j] = zdj;
}

// =====================================================================
// launch
// =====================================================================
extern "C" void kernel_launch(void* const* d_in, const int* in_sizes, int n_in,
                              void* d_out, int out_size)
{
    const float* z0        = (const float*)d_in[0];
    const float* t_dyn     = (const float*)d_in[1];
    const float* Y         = (const float*)d_in[2];
    const float* M         = (const float*)d_in[3];
    const int*   dyn_lens  = (const int*)  d_in[4];
    const float* H         = (const float*)d_in[5];
    const float* W_ih      = (const float*)d_in[6];
    const float* b_ih      = (const float*)d_in[7];
    const float* W_hh      = (const float*)d_in[8];
    const float* b_hh      = (const float*)d_in[9];
    const float* log_gamma = (const float*)d_in[10];

    float* out     = (float*)d_out;
    float* z_final = out;                       // (B, DZ)
    float* Z_traj  = out + (size_t)BB * DZC;    // (B, T, DZ)

    float* gi = nullptr;
    cudaGetSymbolAddress((void**)&gi, g_gi);

    dim3 ggrid((BB * TT) / Bb, GG / BN);        // (1024, 3)
    gi_gemm_kernel<<<ggrid, 256>>>(Y, M, H, W_ih, b_ih, gi);

    gru_scan_kernel<<<BB, 512>>>(z0, t_dyn, dyn_lens, W_hh, b_hh, log_gamma,
                                 z_final, Z_traj);
}

// round 6
// speedup vs baseline: 1.5793x; 1.5793x over previous
#include <cuda_runtime.h>
#include <cuda_bf16.h>
#include <math.h>

// Problem constants
#define BB   32
#define TT   4096
#define DZC  128
#define NDC  32
#define DHC  128
#define GG   384            // 3*DZ
#define IND  192            // 2*ND + DH

#define TBLK      128                 // timesteps per GEMM tile
#define NTBLK     (TT / TBLK)         // 32 t-blocks per batch
#define GEMM_CTAS (NTBLK * BB * 3)    // 3072
#define SCAN_CTAS BB                  // 32

// ---------------- scratch (no cudaMalloc allowed) ----------------
__device__ float        g_gi[(size_t)BB * TT * GG + 2 * GG];  // +2 steps pad
__device__ unsigned int g_cnt[BB * NTBLK];                    // tile counters

// ---------------- packed fp32x2 helpers (sm_100+) ----------------
__device__ __forceinline__ void fma2(unsigned long long& d,
                                     unsigned long long a,
                                     unsigned long long b) {
    asm("fma.rn.f32x2 %0, %1, %2, %0;" : "+l"(d) : "l"(a), "l"(b));
}
__device__ __forceinline__ void add2(unsigned long long& d, unsigned long long a) {
    asm("add.rn.f32x2 %0, %0, %1;" : "+l"(d) : "l"(a));
}
__device__ __forceinline__ unsigned long long dup2(float a) {
    unsigned long long r;
    asm("mov.b64 %0, {%1, %1};" : "=l"(r) : "f"(a));
    return r;
}
__device__ __forceinline__ void unpk(unsigned long long v, float& x, float& y) {
    asm("mov.b64 {%0, %1}, %2;" : "=f"(x), "=f"(y) : "l"(v));
}
__device__ __forceinline__ float ex2f_(float x) {
    float y; asm("ex2.approx.f32 %0, %1;" : "=f"(y) : "f"(x)); return y;
}
__device__ __forceinline__ float rcpf_(float x) {
    float y; asm("rcp.approx.f32 %0, %1;" : "=f"(y) : "f"(x)); return y;
}
__device__ __forceinline__ float sigmoidf_(float x) {
    float e = ex2f_(-1.4426950408889634f * x);
    return rcpf_(1.0f + e);
}
__device__ __forceinline__ float tanhf_(float x) {
    float xc = fminf(fmaxf(x, -20.0f), 20.0f);
    float e = ex2f_(-2.8853900817779268f * xc);   // exp(-2x)
    return (1.0f - e) * rcpf_(1.0f + e);
}
__device__ __forceinline__ unsigned int ldvol_(const unsigned int* p) {
    unsigned int v;
    asm volatile("ld.volatile.global.b32 %0, [%1];" : "=r"(v) : "l"(p));
    return v;
}

// =====================================================================
// Fused kernel. blockIdx.x < 32  -> scan role (one CTA per batch)
//               blockIdx.x >= 32 -> GEMM tile role (t-block-major order)
// =====================================================================
#define Bb 128
#define BN 128
#define BK 16

struct ScanSmem {
    float dtbuf[TT + 4];
    float zbA[DZC];
    float zbB[DZC];
};
struct GemmSmem {
    float As[2][BK][Bb];
    float Bs[2][BK][BN];
};

__global__ __launch_bounds__(256, 1) void fused_kernel(
    const float* __restrict__ z0, const float* __restrict__ t_dyn,
    const int* __restrict__ dyn_lens,
    const float* __restrict__ Y, const float* __restrict__ M,
    const float* __restrict__ H,
    const float* __restrict__ W_ih, const float* __restrict__ b_ih,
    const float* __restrict__ W_hh, const float* __restrict__ b_hh,
    const float* __restrict__ log_gamma,
    float* __restrict__ z_final, float* __restrict__ Z_traj)
{
    __shared__ __align__(16) union { ScanSmem scan; GemmSmem gemm; } sm;

    const int tid = threadIdx.x;

    if (blockIdx.x >= SCAN_CTAS) {
        // ================= GEMM role =================
        // gidx ordered t-block-major so early timesteps finish first
        const int gidx = blockIdx.x - SCAN_CTAS;
        const int tb   = gidx / (BB * 3);
        const int rem  = gidx % (BB * 3);
        const int b    = rem / 3;
        const int gblk = rem % 3;
        const int bt0  = b * TT + tb * TBLK;
        const int g0   = gblk * BN;

        float* gi = g_gi;
        const int tx = tid & 15;
        const int ty = tid >> 4;

        unsigned long long acc[8][4];
        #pragma unroll
        for (int i = 0; i < 8; i++)
            #pragma unroll
            for (int j = 0; j < 4; j++) acc[i][j] = 0ull;

        auto loadA = [&](int stage, int kc) {
            #pragma unroll
            for (int i = 0; i < 2; i++) {
                int e  = tid + 256 * i;
                int m  = e & 127;
                int k4 = e >> 7;
                int kk = kc * BK + k4 * 4;
                int bt = bt0 + m;
                float4 v;
                if (kk < 32)       v = *(const float4*)(Y + (size_t)bt * NDC + kk);
                else if (kk < 64)  v = *(const float4*)(M + (size_t)bt * NDC + (kk - 32));
                else               v = *(const float4*)(H + (size_t)bt * DHC + (kk - 64));
                sm.gemm.As[stage][k4 * 4 + 0][m] = v.x;
                sm.gemm.As[stage][k4 * 4 + 1][m] = v.y;
                sm.gemm.As[stage][k4 * 4 + 2][m] = v.z;
                sm.gemm.As[stage][k4 * 4 + 3][m] = v.w;
            }
        };
        auto loadB = [&](int stage, int kc) {
            #pragma unroll
            for (int i = 0; i < 2; i++) {
                int e  = tid + 256 * i;
                int g  = e & 127;
                int k4 = e >> 7;
                int kk = kc * BK + k4 * 4;
                float4 v = *(const float4*)(W_ih + (size_t)(g0 + g) * IND + kk);
                sm.gemm.Bs[stage][k4 * 4 + 0][g] = v.x;
                sm.gemm.Bs[stage][k4 * 4 + 1][g] = v.y;
                sm.gemm.Bs[stage][k4 * 4 + 2][g] = v.z;
                sm.gemm.Bs[stage][k4 * 4 + 3][g] = v.w;
            }
        };

        loadA(0, 0); loadB(0, 0);
        __syncthreads();

        const int NKC = IND / BK;   // 12
        for (int kc = 0; kc < NKC; kc++) {
            int cur = kc & 1, nxt = cur ^ 1;
            if (kc + 1 < NKC) { loadA(nxt, kc + 1); loadB(nxt, kc + 1); }
            #pragma unroll
            for (int k = 0; k < BK; k++) {
                float a[8];
                *(float4*)&a[0] = *(const float4*)&sm.gemm.As[cur][k][ty * 8];
                *(float4*)&a[4] = *(const float4*)&sm.gemm.As[cur][k][ty * 8 + 4];
                unsigned long long bv[4];
                {
                    ulonglong2 b0 = *(const ulonglong2*)&sm.gemm.Bs[cur][k][tx * 8];
                    ulonglong2 b1 = *(const ulonglong2*)&sm.gemm.Bs[cur][k][tx * 8 + 4];
                    bv[0] = b0.x; bv[1] = b0.y; bv[2] = b1.x; bv[3] = b1.y;
                }
                #pragma unroll
                for (int i = 0; i < 8; i++) {
                    unsigned long long ad = dup2(a[i]);
                    fma2(acc[i][0], ad, bv[0]);
                    fma2(acc[i][1], ad, bv[1]);
                    fma2(acc[i][2], ad, bv[2]);
                    fma2(acc[i][3], ad, bv[3]);
                }
            }
            __syncthreads();
        }

        float bia[8];
        *(float4*)&bia[0] = *(const float4*)(b_ih + g0 + tx * 8);
        *(float4*)&bia[4] = *(const float4*)(b_ih + g0 + tx * 8 + 4);

        #pragma unroll
        for (int i = 0; i < 8; i++) {
            float c[8];
            unpk(acc[i][0], c[0], c[1]);
            unpk(acc[i][1], c[2], c[3]);
            unpk(acc[i][2], c[4], c[5]);
            unpk(acc[i][3], c[6], c[7]);
            #pragma unroll
            for (int j = 0; j < 8; j++) c[j] += bia[j];
            int bt = bt0 + ty * 8 + i;
            float* outp = gi + (size_t)bt * GG + g0 + tx * 8;
            *(float4*)(outp)     = *(float4*)&c[0];
            *(float4*)(outp + 4) = *(float4*)&c[4];
        }

        // publish tile: all stores visible, then bump counter
        __threadfence();
        __syncthreads();
        if (tid == 0) atomicAdd(&g_cnt[b * NTBLK + tb], 1u);
        return;
    }

    // ================= scan role =================
    const int b = blockIdx.x;
    const int j = tid >> 1;     // state dim 0..127
    const int q = tid & 1;      // K-half 0..1

    float* dtbuf = sm.scan.dtbuf;
    float* zbA   = sm.scan.zbA;
    float* zbB   = sm.scan.zbB;

    // dt[t] = max(ts[t]-ts[t-1],0), dt[0]=0, dt[TT]=0
    {
        const float* tp = t_dyn + (size_t)b * TT;
        for (int i = tid; i < TT; i += 256) {
            float cur = __ldg(tp + i);
            float prv = (i > 0) ? __ldg(tp + i - 1) : cur;
            dtbuf[i] = fmaxf(cur - prv, 0.0f);
        }
        if (tid == 0) dtbuf[TT] = 0.0f;
    }

    // weights: rows {j, 128+j, 256+j}, K half [64q, 64q+64)
    unsigned long long Wr[32], Wu[32], Wn[32];
    {
        const ulonglong2* wr = (const ulonglong2*)(W_hh + (size_t)j * DZC + 64 * q);
        const ulonglong2* wu = (const ulonglong2*)(W_hh + (size_t)(128 + j) * DZC + 64 * q);
        const ulonglong2* wn = (const ulonglong2*)(W_hh + (size_t)(256 + j) * DZC + 64 * q);
        #pragma unroll
        for (int i = 0; i < 16; i++) {
            ulonglong2 a = wr[i]; Wr[2*i] = a.x; Wr[2*i+1] = a.y;
            ulonglong2 c = wu[i]; Wu[2*i] = c.x; Wu[2*i+1] = c.y;
            ulonglong2 d = wn[i]; Wn[2*i] = d.x; Wn[2*i+1] = d.y;
        }
    }
    const float bh_own = (q == 0) ? b_hh[j] : b_hh[128 + j];
    const float bh_n   = (q == 0) ? b_hh[256 + j] : 0.0f;
    const int   len = dyn_lens[b];

    float lg  = log_gamma[j];
    float sp  = (lg > 20.0f) ? lg : log1pf(expf(lg));   // softplus
    const float gje = -1.4426950408889634f * sp;

    const unsigned int* cntp = &g_cnt[b * NTBLK];

    // wait for t-block 0 of this batch (3 g-tiles)
    while (ldvol_(cntp + 0) < 3u) { }
    __threadfence();   // acquire: order subsequent gi loads after the check

    // gi streams: own gate row (q0->r, q1->u) and n row (both lanes)
    const float* pG = g_gi + (size_t)b * TT * GG + q * DZC + j;
    const float* pN = g_gi + (size_t)b * TT * GG + 2 * DZC + j;
    float gi_c = __ldg(pG), gi_1 = __ldg(pG + GG);
    float gn_c = __ldg(pN), gn_1 = __ldg(pN + GG);
    pG += 2 * GG;
    pN += 2 * GG;

    float* zp = Z_traj + (size_t)b * TT * DZC + j;

    float zdj = z0[(size_t)b * DZC + j];
    if (q == 0) zbA[j] = zdj;

    auto step = [&](int t, const float* __restrict__ zr, float* __restrict__ zw) {
        __syncthreads();   // zr(t) visible; zw free (double-buffer WAR-safe)

        // gate the t+2 prefetch on producer progress at t-block boundaries
        int tt = t + 2;
        if ((tt & (TBLK - 1)) == 0 && tt < TT) {
            while (ldvol_(cntp + (tt >> 7)) < 3u) { }
            __threadfence();
        }
        float edn  = ex2f_(gje * dtbuf[t + 1]);
        float gi_2 = __ldg(pG);
        float gn_2 = __ldg(pN);
        pG += GG; pN += GG;

        const ulonglong2* zc = (const ulonglong2*)(zr + 64 * q);

        // ---- phase 1: r,u gates (64 fma2) ----
        unsigned long long ar0 = 0, ar1 = 0, au0 = 0, au1 = 0;
        #pragma unroll
        for (int i = 0; i < 16; i += 2) {
            ulonglong2 v0 = zc[i];
            ulonglong2 v1 = zc[i + 1];
            fma2(ar0, Wr[2*i],   v0.x); fma2(ar0, Wr[2*i+1], v0.y);
            fma2(au0, Wu[2*i],   v0.x); fma2(au0, Wu[2*i+1], v0.y);
            fma2(ar1, Wr[2*i+2], v1.x); fma2(ar1, Wr[2*i+3], v1.y);
            fma2(au1, Wu[2*i+2], v1.x); fma2(au1, Wu[2*i+3], v1.y);
        }
        add2(ar0, ar1); add2(au0, au1);
        float r0, r1, u0, u1;
        unpk(ar0, r0, r1); unpk(au0, u0, u1);
        float Sr = r0 + r1, Su = u0 + u1;
        if (q == 0) Sr += gi_c + bh_own;
        else        Su += gi_c + bh_own;
        // issue the r,u reduces early; their latency hides under phase 2
        Sr += __shfl_xor_sync(0xffffffffu, Sr, 1);
        Su += __shfl_xor_sync(0xffffffffu, Su, 1);

        // ---- phase 2: n gate (32 fma2, z chunks re-read: broadcast LDS) ----
        unsigned long long an0 = 0, an1 = 0;
        #pragma unroll
        for (int i = 0; i < 16; i += 2) {
            ulonglong2 v0 = zc[i];
            ulonglong2 v1 = zc[i + 1];
            fma2(an0, Wn[2*i],   v0.x); fma2(an0, Wn[2*i+1], v0.y);
            fma2(an1, Wn[2*i+2], v1.x); fma2(an1, Wn[2*i+3], v1.y);
        }
        add2(an0, an1);
        float n0, n1;
        unpk(an0, n0, n1);
        float Sn = n0 + n1;
        if (q == 0) Sn += bh_n;
        Sn += __shfl_xor_sync(0xffffffffu, Sn, 1);

        float rr = sigmoidf_(Sr);
        float uu = sigmoidf_(Su);
        float nn = tanhf_(gn_c + rr * Sn);
        float znew = nn + uu * (zdj - nn);
        float zj   = (t < len) ? znew : zdj;
        if (q == 0) *zp = zj;
        zp += DZC;

        zdj = zj * edn;            // z_d for t+1 (dt[TT]=0 -> edn=1 at tail)
        if (q == 0) zw[j] = zdj;

        gi_c = gi_1; gi_1 = gi_2;
        gn_c = gn_1; gn_1 = gn_2;
    };

    for (int t = 0; t < TT; t += 2) {
        step(t,     zbA, zbB);
        step(t + 1, zbB, zbA);
    }

    if (q == 0) z_final[(size_t)b * DZC + j] = zdj;   // edn(last)=1 -> zdj==zj
}

// =====================================================================
// launch
// =====================================================================
extern "C" void kernel_launch(void* const* d_in, const int* in_sizes, int n_in,
                              void* d_out, int out_size)
{
    const float* z0        = (const float*)d_in[0];
    const float* t_dyn     = (const float*)d_in[1];
    const float* Y         = (const float*)d_in[2];
    const float* M         = (const float*)d_in[3];
    const int*   dyn_lens  = (const int*)  d_in[4];
    const float* H         = (const float*)d_in[5];
    const float* W_ih      = (const float*)d_in[6];
    const float* b_ih      = (const float*)d_in[7];
    const float* W_hh      = (const float*)d_in[8];
    const float* b_hh      = (const float*)d_in[9];
    const float* log_gamma = (const float*)d_in[10];

    float* out     = (float*)d_out;
    float* z_final = out;                       // (B, DZ)
    float* Z_traj  = out + (size_t)BB * DZC;    // (B, T, DZ)

    void* cnt_ptr = nullptr;
    cudaGetSymbolAddress(&cnt_ptr, g_cnt);
    cudaMemsetAsync(cnt_ptr, 0, sizeof(unsigned int) * BB * NTBLK);

    fused_kernel<<<SCAN_CTAS + GEMM_CTAS, 256>>>(
        z0, t_dyn, dyn_lens, Y, M, H, W_ih, b_ih, W_hh, b_hh, log_gamma,
        z_final, Z_traj);
}